// round 2
// baseline (speedup 1.0000x reference)
#include <cuda_runtime.h>

#define NH 128
#define NI 64
#define NO 10
#define NB 128
#define NT 512   // 4 partial-threads per hidden column

// Persistent per-batch-chain RNN scan, 4-way split dot products.
// grid = 128 CTAs (one batch row each), block = 512.
// Thread t: column j = t>>2, partial p = t&3. The 4 partials of a column are
// lanes {4q, 4q+1, 4q+2, 4q+3} of one warp -> shfl_xor reduction, no barrier.
// Weight slices are stride-interleaved so the quad's LDS.128 reads hit 16
// distinct banks (conflict-free broadcast).
__global__ void __launch_bounds__(NT, 1) rnn_scan_kernel(
    const float* __restrict__ x,    // [S, B, NI]
    const float* __restrict__ Wxh,  // [NI, NH]
    const float* __restrict__ Whh,  // [NH, NH]
    const float* __restrict__ Why,  // [NH, NO]
    const float* __restrict__ bh,   // [NH]
    const float* __restrict__ by,   // [NO]
    float* __restrict__ out,        // logits [B,NO] then h [S,B,NH]
    int seq)
{
    const int b   = blockIdx.x;
    const int tid = threadIdx.x;
    const int j   = tid >> 2;   // hidden column
    const int p   = tid & 3;    // partial index

    // ---- weight slices into registers (12 float4 = 48 regs) ----
    // h-part: groups m=0..7, rows k = 16m+4p .. +3 of Whh[:,j]
    // x-part: groups m=0..3, rows i = 16m+4p .. +3 of Wxh[:,j]
    float4 wh[8], wx[4];
#pragma unroll
    for (int m = 0; m < 8; m++) {
        int k = 16 * m + 4 * p;
        wh[m].x = Whh[(k + 0) * NH + j];
        wh[m].y = Whh[(k + 1) * NH + j];
        wh[m].z = Whh[(k + 2) * NH + j];
        wh[m].w = Whh[(k + 3) * NH + j];
    }
#pragma unroll
    for (int m = 0; m < 4; m++) {
        int i = 16 * m + 4 * p;
        wx[m].x = Wxh[(i + 0) * NH + j];
        wx[m].y = Wxh[(i + 1) * NH + j];
        wx[m].z = Wxh[(i + 2) * NH + j];
        wx[m].w = Wxh[(i + 3) * NH + j];
    }
    const float bias = bh[j];

    __shared__ __align__(16) float hsh[2][NH];
    __shared__ __align__(16) float xsh[2][NI];

    if (tid < NH) hsh[0][tid] = 0.0f;

    const float* xbase = x + (long long)b * NI;

    // preload x(0)
    if (tid < NI / 4) {
        reinterpret_cast<float4*>(xsh[0])[tid] =
            reinterpret_cast<const float4*>(xbase)[tid];
    }
    __syncthreads();

    // pipeline register holds x(t+1); STS at top of step t, LDG refills x(t+2)
    float4 xr = make_float4(0.f, 0.f, 0.f, 0.f);
    if (tid < NI / 4 && seq > 1) {
        xr = reinterpret_cast<const float4*>(xbase + (long long)NB * NI)[tid];
    }

    float* h_out = out + NB * NO;
    int hb = 0;

    for (int t = 0; t < seq; t++) {
        // ---- x prefetch pipeline (threads 0..15) ----
        if (tid < NI / 4) {
            reinterpret_cast<float4*>(xsh[(t + 1) & 1])[tid] = xr;
            if (t + 2 < seq) {
                xr = reinterpret_cast<const float4*>(
                         xbase + (long long)(t + 2) * NB * NI)[tid];
            }
        }

        // ---- 48-term partial dot ----
        const float4* h4 = reinterpret_cast<const float4*>(hsh[hb]);
        const float4* x4 = reinterpret_cast<const float4*>(xsh[t & 1]);
        float a0 = 0.f, a1 = 0.f, a2 = 0.f, a3 = 0.f;
#pragma unroll
        for (int m = 0; m < 8; m++) {
            float4 hv = h4[4 * m + p];          // word offset 16m+4p: no conflicts
            a0 = fmaf(hv.x, wh[m].x, a0);
            a1 = fmaf(hv.y, wh[m].y, a1);
            a2 = fmaf(hv.z, wh[m].z, a2);
            a3 = fmaf(hv.w, wh[m].w, a3);
        }
#pragma unroll
        for (int m = 0; m < 4; m++) {
            float4 xv = x4[4 * m + p];
            a0 = fmaf(xv.x, wx[m].x, a0);
            a1 = fmaf(xv.y, wx[m].y, a1);
            a2 = fmaf(xv.z, wx[m].z, a2);
            a3 = fmaf(xv.w, wx[m].w, a3);
        }
        float v = (a0 + a1) + (a2 + a3);

        // ---- butterfly reduce over the 4 partials (same warp) ----
        v += __shfl_xor_sync(0xffffffffu, v, 1);
        v += __shfl_xor_sync(0xffffffffu, v, 2);
        v += bias;

        // ---- accurate tanh (all 4 lanes redundantly; keeps warp uniform) ----
        float a = fabsf(v);
        float e = __expf(-2.0f * a);
        float r = (1.0f - e) / (1.0f + e);
        float h = copysignf(r, v);

        if (p == 0) {
            hsh[hb ^ 1][j] = h;
            h_out[((long long)t * NB + b) * NH + j] = h;
        }
        __syncthreads();
        hb ^= 1;
    }

    // ---- logits = h_last @ Why + by ----
    if (tid < NO) {
        float acc = by[tid];
#pragma unroll 8
        for (int k = 0; k < NH; k++)
            acc = fmaf(hsh[hb][k], Why[k * NO + tid], acc);
        out[b * NO + tid] = acc;
    }
}

extern "C" void kernel_launch(void* const* d_in, const int* in_sizes, int n_in,
                              void* d_out, int out_size) {
    const float* x   = (const float*)d_in[0];
    const float* Wxh = (const float*)d_in[1];
    const float* Whh = (const float*)d_in[2];
    const float* Why = (const float*)d_in[3];
    const float* bh  = (const float*)d_in[4];
    const float* by  = (const float*)d_in[5];
    float* out = (float*)d_out;

    int seq = in_sizes[0] / (NB * NI);  // 2048

    rnn_scan_kernel<<<NB, NT>>>(x, Wxh, Whh, Why, bh, by, out, seq);
}

// round 3
// speedup vs baseline: 1.4154x; 1.4154x over previous
#include <cuda_runtime.h>

#define NH 128
#define NI 64
#define NO 10
#define NB 128
#define S_MAX 2048

// 128 MiB scratch for the precomputed input projection xW[S,B,H].
__device__ __align__(16) float g_xw[(size_t)S_MAX * NB * NH];

// ---- packed f32x2 helpers (sm_100+ PTX) ----
__device__ __forceinline__ unsigned long long ffma2(unsigned long long a,
                                                    unsigned long long b,
                                                    unsigned long long c) {
    unsigned long long d;
    asm("fma.rn.f32x2 %0, %1, %2, %3;" : "=l"(d) : "l"(a), "l"(b), "l"(c));
    return d;
}
__device__ __forceinline__ unsigned long long packf2(float lo, float hi) {
    unsigned long long r;
    asm("mov.b64 %0, {%1, %2};" : "=l"(r) : "f"(lo), "f"(hi));
    return r;
}
__device__ __forceinline__ float2 unpackf2(unsigned long long v) {
    float2 f;
    asm("mov.b64 {%0, %1}, %2;" : "=f"(f.x), "=f"(f.y) : "l"(v));
    return f;
}

// ============================================================
// K1: xW[s,b,j] = x[s,b,:] @ Wxh[:,j] + bh[j]
// grid = seq, block = 256 (p = tid>>7 splits batch rows, j = tid&127)
// ============================================================
__global__ void __launch_bounds__(256, 1) xw_gemm_kernel(
    const float* __restrict__ x, const float* __restrict__ Wxh,
    const float* __restrict__ bh, int seq)
{
    const int s = blockIdx.x;
    __shared__ __align__(16) float xs[NB * NI];  // 32 KB: x[s,:,:]

    const float4* xin = reinterpret_cast<const float4*>(x + (long long)s * NB * NI);
    float4* xs4 = reinterpret_cast<float4*>(xs);
#pragma unroll
    for (int i = threadIdx.x; i < NB * NI / 4; i += 256) xs4[i] = xin[i];

    const int j = threadIdx.x & 127;
    const int p = threadIdx.x >> 7;

    unsigned long long w2[NI / 2];
#pragma unroll
    for (int m = 0; m < NI / 2; m++)
        w2[m] = packf2(Wxh[(2 * m) * NH + j], Wxh[(2 * m + 1) * NH + j]);
    const unsigned long long bias2 = packf2(bh[j], 0.0f);
    __syncthreads();

    float* outrow = g_xw + (long long)s * NB * NH;
    for (int b = p; b < NB; b += 2) {
        const ulonglong2* xr = reinterpret_cast<const ulonglong2*>(xs + b * NI);
        unsigned long long a0 = bias2, a1 = 0ull, a2 = 0ull, a3 = 0ull;
#pragma unroll
        for (int m = 0; m < NI / 4; m++) {  // 16 iters: 16 LDS.128, 32 FFMA2
            ulonglong2 xv = xr[m];
            if (m & 1) { a2 = ffma2(xv.x, w2[2 * m], a2); a3 = ffma2(xv.y, w2[2 * m + 1], a3); }
            else       { a0 = ffma2(xv.x, w2[2 * m], a0); a1 = ffma2(xv.y, w2[2 * m + 1], a1); }
        }
        float2 f0 = unpackf2(a0), f1 = unpackf2(a1), f2 = unpackf2(a2), f3 = unpackf2(a3);
        outrow[b * NH + j] =
            ((f0.x + f0.y) + (f1.x + f1.y)) + ((f2.x + f2.y) + (f3.x + f3.y));
    }
}

// ============================================================
// K2: the sequential scan. grid = NB, block = NH.
// Thread j owns column j: 128-term dot as 64 FFMA2 + 32 LDS.128/step.
// ============================================================
__global__ void __launch_bounds__(NH, 1) rnn_scan_kernel(
    const float* __restrict__ Whh, const float* __restrict__ Why,
    const float* __restrict__ by, float* __restrict__ out, int seq)
{
    const int b = blockIdx.x;
    const int j = threadIdx.x;

    // Whh column j, pre-packed to match ulonglong2 (LDS.128) h pairs
    unsigned long long w2[NH / 2];
#pragma unroll
    for (int k = 0; k < NH / 2; k++)
        w2[k] = packf2(Whh[(2 * k) * NH + j], Whh[(2 * k + 1) * NH + j]);

    __shared__ __align__(16) float hsh[2][NH];
    hsh[0][j] = 0.0f;

    // xw prefetch ring, depth 4 (~4 steps ≈ 900+ cyc of DRAM latency cover)
    const float* xwb = g_xw + (long long)b * NH + j;
    float xq[4];
#pragma unroll
    for (int q = 0; q < 4; q++)
        xq[q] = (q < seq) ? xwb[(long long)q * NB * NH] : 0.0f;

    float* h_out = out + NB * NO;
    __syncthreads();

    int hb = 0;
#pragma unroll 4
    for (int t = 0; t < seq; t++) {
        unsigned long long a0 = packf2(xq[t & 3], 0.0f);
        unsigned long long a1 = 0ull, a2 = 0ull, a3 = 0ull;
        if (t + 4 < seq)
            xq[t & 3] = xwb[(long long)(t + 4) * NB * NH];

        const ulonglong2* h2 = reinterpret_cast<const ulonglong2*>(hsh[hb]);
#pragma unroll
        for (int m = 0; m < NH / 4; m++) {  // 32 iters: 32 LDS.128, 64 FFMA2
            ulonglong2 hv = h2[m];
            if (m & 1) { a2 = ffma2(hv.x, w2[2 * m], a2); a3 = ffma2(hv.y, w2[2 * m + 1], a3); }
            else       { a0 = ffma2(hv.x, w2[2 * m], a0); a1 = ffma2(hv.y, w2[2 * m + 1], a1); }
        }
        float2 f0 = unpackf2(a0), f1 = unpackf2(a1), f2 = unpackf2(a2), f3 = unpackf2(a3);
        float v = ((f0.x + f0.y) + (f1.x + f1.y)) + ((f2.x + f2.y) + (f3.x + f3.y));

        // accurate tanh via exp2/rcp (MUFU); approx-tanh's 1e-3 abs error
        // would random-walk past tolerance over 2048 steps
        float a = fabsf(v);
        float e = __expf(-2.0f * a);
        float h = copysignf((1.0f - e) / (1.0f + e), v);

        h_out[((long long)t * NB + b) * NH + j] = h;  // coalesced 512 B
        hsh[hb ^ 1][j] = h;
        __syncthreads();
        hb ^= 1;
    }

    // logits = h_last @ Why + by
    if (j < NO) {
        float acc = by[j];
#pragma unroll 8
        for (int k = 0; k < NH; k++)
            acc = fmaf(hsh[hb][k], Why[k * NO + j], acc);
        out[b * NO + j] = acc;
    }
}

extern "C" void kernel_launch(void* const* d_in, const int* in_sizes, int n_in,
                              void* d_out, int out_size) {
    const float* x   = (const float*)d_in[0];
    const float* Wxh = (const float*)d_in[1];
    const float* Whh = (const float*)d_in[2];
    const float* Why = (const float*)d_in[3];
    const float* bh  = (const float*)d_in[4];
    const float* by  = (const float*)d_in[5];
    float* out = (float*)d_out;

    int seq = in_sizes[0] / (NB * NI);  // 2048
    if (seq > S_MAX) seq = S_MAX;

    xw_gemm_kernel<<<seq, 256>>>(x, Wxh, bh, seq);
    rnn_scan_kernel<<<NB, NH>>>(Whh, Why, by, out, seq);
}